// round 6
// baseline (speedup 1.0000x reference)
#include <cuda_runtime.h>
#include <math.h>
#include <stdint.h>

// ---------------- problem constants ----------------
#define N_MAX   50000
#define E_MAX   800000
#define IN_CH   128
#define HIDC    32
#define H1CH    128      // heads1 * hid
#define CATCH   160
#define OUTCH   64
#define NEG_SLOPE 0.2f
#define BN_EPS    1e-5f

// ---------------- device scratch (no allocs allowed) ----------------
__device__ float g_xlr1[N_MAX * 256];   // [xl1 | xr1] per row
__device__ float g_h1  [N_MAX * H1CH];
__device__ float g_xlr2[N_MAX * 64];
__device__ float g_h2e [N_MAX * HIDC];
__device__ float g_w1cat[128 * 256];
__device__ float g_w2cat[128 * 64];

__device__ int   g_counts[N_MAX];
__device__ int   g_rowptr[N_MAX + 1];
__device__ int   g_srcs  [E_MAX];

__device__ float g_sum  [H1CH];
__device__ float g_sumsq[H1CH];
__device__ float g_scale[H1CH];
__device__ float g_shift[H1CH];

// ---------------- helpers ----------------
__device__ __forceinline__ float lrelu(float v) { return v > 0.f ? v : NEG_SLOPE * v; }
__device__ __forceinline__ float eluf(float v)  { return v > 0.f ? v : expm1f(v); }

__device__ __forceinline__ uint32_t f2tf32(float f) {
    uint32_t u;
    asm("cvt.rna.tf32.f32 %0, %1;" : "=r"(u) : "f"(f));
    return u;
}

__device__ __forceinline__ uint4 f4_to_tf32(float4 v) {
    uint4 r;
    r.x = f2tf32(v.x); r.y = f2tf32(v.y); r.z = f2tf32(v.z); r.w = f2tf32(v.w);
    return r;
}

__device__ __forceinline__ void mma_m16n8k8(float* c, const uint32_t* a, const uint32_t* b) {
    asm volatile(
        "mma.sync.aligned.m16n8k8.row.col.f32.tf32.tf32.f32 "
        "{%0,%1,%2,%3}, {%4,%5,%6,%7}, {%8,%9}, {%0,%1,%2,%3};\n"
        : "+f"(c[0]), "+f"(c[1]), "+f"(c[2]), "+f"(c[3])
        : "r"(a[0]), "r"(a[1]), "r"(a[2]), "r"(a[3]), "r"(b[0]), "r"(b[1]));
}

// ---------------- prep: zero counters + concat weights ----------------
__global__ void k_prep(const float* __restrict__ W1l, const float* __restrict__ W1r,
                       const float* __restrict__ W2l, const float* __restrict__ W2r, int n) {
    int i = blockIdx.x * blockDim.x + threadIdx.x;
    if (i < n) g_counts[i] = 0;
    if (i < H1CH) { g_sum[i] = 0.f; g_sumsq[i] = 0.f; }
    if (i < 128 * 256) {
        int k = i >> 8, j = i & 255;
        g_w1cat[i] = (j < 128) ? W1l[k * 128 + j] : W1r[k * 128 + j - 128];
    }
    if (i < 128 * 64) {
        int k = i >> 6, j = i & 63;
        g_w2cat[i] = (j < 32) ? W2l[k * 32 + j] : W2r[k * 32 + (j - 32)];
    }
}

// ---------------- CSR build ----------------
__global__ void k_count(const int* __restrict__ ei, int e) {
    int i = blockIdx.x * blockDim.x + threadIdx.x;
    if (i < e) atomicAdd(&g_counts[ei[e + i]], 1);
}

// single-block chunked exclusive scan: counts -> rowptr, re-zero counts
__global__ void k_scan_all(int n, int e) {
    const int T = 1024;
    int t = threadIdx.x;
    int chunk = (n + T - 1) / T;
    int s0 = t * chunk;
    int s1 = min(s0 + chunk, n);

    int local = 0;
    for (int i = s0; i < s1; i++) local += g_counts[i];

    int lane = t & 31, w = t >> 5;

    // warp-level inclusive scan of per-thread sums
    int inc = local;
#pragma unroll
    for (int off = 1; off < 32; off <<= 1) {
        int u = __shfl_up_sync(0xffffffffu, inc, off);
        if (lane >= off) inc += u;
    }

    __shared__ int wsum[32];
    if (lane == 31) wsum[w] = inc;          // warp totals
    __syncthreads();

    if (w == 0) {                           // warp 0: inclusive scan of warp totals, in place
        int v = wsum[lane];
#pragma unroll
        for (int off = 1; off < 32; off <<= 1) {
            int u = __shfl_up_sync(0xffffffffu, v, off);
            if (lane >= off) v += u;
        }
        wsum[lane] = v;
    }
    __syncthreads();

    int base = (w == 0) ? 0 : wsum[w - 1];
    int run = base + inc - local;           // exclusive prefix for this thread's chunk

    for (int i = s0; i < s1; i++) {
        int c = g_counts[i];
        g_rowptr[i] = run;
        run += c;
        g_counts[i] = 0;
    }
    if (t == 0) g_rowptr[n] = e;
}

__global__ void k_fill(const int* __restrict__ ei, int e) {
    int i = blockIdx.x * blockDim.x + threadIdx.x;
    if (i < e) {
        int d = ei[e + i];
        int s = ei[i];
        int pos = g_rowptr[d] + atomicAdd(&g_counts[d], 1);
        g_srcs[pos] = s;
    }
}

// ---------------- tf32 MMA GEMM (smem holds tf32 bits) ----------------
// MODE 0: A = plain fp32 pointer
// MODE 1: A = elu(bn(g_h1))   (K=128)
// MODE 2: A = [g_h2e | xcat]  (K=160)
template <int BM, int BN, int WM_CNT, int WN_CNT, int MODE>
__device__ __forceinline__ void mma_gemm_body(
    const float* __restrict__ A, const float* __restrict__ B,
    float* __restrict__ C, int M, int K, int ldb, int ldc,
    const float* __restrict__ bias, const float* __restrict__ xcat)
{
    constexpr int BK = 32;
    constexpr int THREADS = WM_CNT * WN_CNT * 32;
    constexpr int WM = BM / WM_CNT;
    constexpr int WN = BN / WN_CNT;
    constexpr int MT = WM / 16;
    constexpr int NT = WN / 8;
    constexpr int LDA = BK + 4;
    constexpr int LDB = BN + 8;

    __shared__ uint32_t As[BM][LDA];
    __shared__ uint32_t Bs[BK][LDB];

    const int tid = threadIdx.x;
    const int wid = tid >> 5;
    const int lane = tid & 31;
    const int warpM = wid / WN_CNT;
    const int warpN = wid % WN_CNT;
    const int g = lane >> 2;
    const int tg = lane & 3;

    const int rowBase = blockIdx.x * BM;
    const int colBase = blockIdx.y * BN;

    float acc[MT][NT][4];
#pragma unroll
    for (int mt = 0; mt < MT; mt++)
#pragma unroll
        for (int nt = 0; nt < NT; nt++)
#pragma unroll
            for (int i = 0; i < 4; i++) acc[mt][nt][i] = 0.f;

    for (int kt = 0; kt < K; kt += BK) {
        constexpr int A_F4 = BM * BK / 4;
#pragma unroll
        for (int it = 0; it < A_F4 / THREADS; it++) {
            int f = tid + it * THREADS;
            int r = f >> 3;
            int kq = (f & 7) << 2;
            int grow = rowBase + r;
            float4 v = make_float4(0.f, 0.f, 0.f, 0.f);
            if (grow < M) {
                if (MODE == 0) {
                    v = *reinterpret_cast<const float4*>(A + (size_t)grow * K + kt + kq);
                } else if (MODE == 1) {
                    v = *reinterpret_cast<const float4*>(&g_h1[(size_t)grow * 128 + kt + kq]);
                    int c = kt + kq;
                    v.x = eluf(fmaf(v.x, g_scale[c + 0], g_shift[c + 0]));
                    v.y = eluf(fmaf(v.y, g_scale[c + 1], g_shift[c + 1]));
                    v.z = eluf(fmaf(v.z, g_scale[c + 2], g_shift[c + 2]));
                    v.w = eluf(fmaf(v.w, g_scale[c + 3], g_shift[c + 3]));
                } else {
                    if (kt == 0)
                        v = *reinterpret_cast<const float4*>(&g_h2e[(size_t)grow * 32 + kq]);
                    else
                        v = *reinterpret_cast<const float4*>(&xcat[(size_t)grow * 128 + kt - 32 + kq]);
                }
            }
            *reinterpret_cast<uint4*>(&As[r][kq]) = f4_to_tf32(v);
        }
        constexpr int B_F4 = BK * BN / 4;
#pragma unroll
        for (int it = 0; it < B_F4 / THREADS; it++) {
            int f = tid + it * THREADS;
            int kr = f / (BN / 4);
            int nq = (f % (BN / 4)) << 2;
            float4 v = *reinterpret_cast<const float4*>(B + (size_t)(kt + kr) * ldb + colBase + nq);
            *reinterpret_cast<uint4*>(&Bs[kr][nq]) = f4_to_tf32(v);
        }
        __syncthreads();

#pragma unroll
        for (int kk = 0; kk < BK; kk += 8) {
            uint32_t af[MT][4];
#pragma unroll
            for (int mt = 0; mt < MT; mt++) {
                int m = warpM * WM + mt * 16;
                af[mt][0] = As[m + g][kk + tg];
                af[mt][1] = As[m + g + 8][kk + tg];
                af[mt][2] = As[m + g][kk + tg + 4];
                af[mt][3] = As[m + g + 8][kk + tg + 4];
            }
            uint32_t bf[NT][2];
#pragma unroll
            for (int nt = 0; nt < NT; nt++) {
                int nn = warpN * WN + nt * 8;
                bf[nt][0] = Bs[kk + tg][nn + g];
                bf[nt][1] = Bs[kk + tg + 4][nn + g];
            }
#pragma unroll
            for (int mt = 0; mt < MT; mt++)
#pragma unroll
                for (int nt = 0; nt < NT; nt++)
                    mma_m16n8k8(acc[mt][nt], af[mt], bf[nt]);
        }
        __syncthreads();
    }

#pragma unroll
    for (int mt = 0; mt < MT; mt++) {
        int m0 = rowBase + warpM * WM + mt * 16 + g;
        int m1 = m0 + 8;
#pragma unroll
        for (int nt = 0; nt < NT; nt++) {
            int c0 = colBase + warpN * WN + nt * 8 + 2 * tg;
            float bx = 0.f, by = 0.f;
            if (bias) { bx = bias[c0]; by = bias[c0 + 1]; }
            if (m0 < M) {
                float2 v = make_float2(acc[mt][nt][0] + bx, acc[mt][nt][1] + by);
                *reinterpret_cast<float2*>(&C[(size_t)m0 * ldc + c0]) = v;
            }
            if (m1 < M) {
                float2 v = make_float2(acc[mt][nt][2] + bx, acc[mt][nt][3] + by);
                *reinterpret_cast<float2*>(&C[(size_t)m1 * ldc + c0]) = v;
            }
        }
    }
}

__global__ void __launch_bounds__(256) k_gemm1(const float* __restrict__ x, int M) {
    mma_gemm_body<128, 128, 2, 4, 0>(x, g_w1cat, g_xlr1, M, 128, 256, 256, nullptr, nullptr);
}
__global__ void __launch_bounds__(256) k_gemm2(int M) {
    mma_gemm_body<128, 64, 4, 2, 1>(nullptr, g_w2cat, g_xlr2, M, 128, 64, 64, nullptr, nullptr);
}
__global__ void __launch_bounds__(256) k_gemm3(const float* __restrict__ Wc,
                                               const float* __restrict__ bc,
                                               const float* __restrict__ x,
                                               float* __restrict__ out, int M) {
    mma_gemm_body<128, 64, 4, 2, 2>(nullptr, Wc, out, M, 160, 64, 64, bc, x);
}

// ---------------- GAT layer 1: warp-per-node, online softmax, prefetch ----------------
__global__ void k_gat1_agg(const float* __restrict__ att1, const float* __restrict__ b1, int n) {
    int node = blockIdx.x * (blockDim.x >> 5) + (threadIdx.x >> 5);
    if (node >= n) return;
    int lane = threadIdx.x & 31;

    const float4* xlr = reinterpret_cast<const float4*>(g_xlr1);

    float4 xrv = xlr[node * 64 + 32 + lane];
    float4 attv = *reinterpret_cast<const float4*>(att1 + (lane >> 3) * HIDC + (lane & 7) * 4);

    // self loop first
    float4 msg = xlr[node * 64 + lane];
    float p = lrelu(msg.x + xrv.x) * attv.x + lrelu(msg.y + xrv.y) * attv.y +
              lrelu(msg.z + xrv.z) * attv.z + lrelu(msg.w + xrv.w) * attv.w;
    p += __shfl_xor_sync(0xffffffffu, p, 1);
    p += __shfl_xor_sync(0xffffffffu, p, 2);
    p += __shfl_xor_sync(0xffffffffu, p, 4);

    float m = p;
    float lsum = 1.f;
    float4 acc = msg;

    int beg = g_rowptr[node];
    int end = g_rowptr[node + 1];

    float4 nmsg = make_float4(0.f, 0.f, 0.f, 0.f);
    if (beg < end) nmsg = xlr[g_srcs[beg] * 64 + lane];

    for (int i = beg; i < end; i++) {
        float4 cur = nmsg;
        if (i + 1 < end) nmsg = xlr[g_srcs[i + 1] * 64 + lane];   // prefetch next edge
        float q = lrelu(cur.x + xrv.x) * attv.x + lrelu(cur.y + xrv.y) * attv.y +
                  lrelu(cur.z + xrv.z) * attv.z + lrelu(cur.w + xrv.w) * attv.w;
        q += __shfl_xor_sync(0xffffffffu, q, 1);
        q += __shfl_xor_sync(0xffffffffu, q, 2);
        q += __shfl_xor_sync(0xffffffffu, q, 4);
        float mn = fmaxf(m, q);
        float sc = __expf(m - mn);
        float w = __expf(q - mn);
        lsum = lsum * sc + w;
        acc.x = acc.x * sc + w * cur.x;
        acc.y = acc.y * sc + w * cur.y;
        acc.z = acc.z * sc + w * cur.z;
        acc.w = acc.w * sc + w * cur.w;
        m = mn;
    }

    float inv = 1.f / lsum;
    float4 bvv = *reinterpret_cast<const float4*>(b1 + lane * 4);
    float4 o;
    o.x = acc.x * inv + bvv.x;
    o.y = acc.y * inv + bvv.y;
    o.z = acc.z * inv + bvv.z;
    o.w = acc.w * inv + bvv.w;
    reinterpret_cast<float4*>(g_h1)[node * 32 + lane] = o;
}

// ---------------- BatchNorm stats ----------------
__global__ void k_bn_stats(int n) {
    int c = threadIdx.x;  // 128 threads
    float s = 0.f, q = 0.f;
    for (int r = blockIdx.x; r < n; r += gridDim.x) {
        float v = g_h1[(size_t)r * H1CH + c];
        s += v;
        q += v * v;
    }
    atomicAdd(&g_sum[c], s);
    atomicAdd(&g_sumsq[c], q);
}

__global__ void k_bn_final(const float* __restrict__ gamma, const float* __restrict__ beta, int n) {
    int c = threadIdx.x;
    if (c < H1CH) {
        float mu = g_sum[c] / (float)n;
        float var = g_sumsq[c] / (float)n - mu * mu;
        float rs = rsqrtf(var + BN_EPS);
        float sc = rs * gamma[c];
        g_scale[c] = sc;
        g_shift[c] = beta[c] - mu * sc;
    }
}

// ---------------- GAT layer 2 (1 head, 32 ch), prefetch ----------------
__global__ void k_gat2_agg(const float* __restrict__ att2, const float* __restrict__ b2, int n) {
    int node = blockIdx.x * (blockDim.x >> 5) + (threadIdx.x >> 5);
    if (node >= n) return;
    int lane = threadIdx.x & 31;

    float xrc = g_xlr2[node * 64 + 32 + lane];
    float ac = att2[lane];

    float msg = g_xlr2[node * 64 + lane];
    float p = lrelu(msg + xrc) * ac;
#pragma unroll
    for (int off = 16; off >= 1; off >>= 1) p += __shfl_xor_sync(0xffffffffu, p, off);

    float m = p, lsum = 1.f, acc = msg;

    int beg = g_rowptr[node];
    int end = g_rowptr[node + 1];

    float nmsg = 0.f;
    if (beg < end) nmsg = g_xlr2[g_srcs[beg] * 64 + lane];

    for (int i = beg; i < end; i++) {
        float cur = nmsg;
        if (i + 1 < end) nmsg = g_xlr2[g_srcs[i + 1] * 64 + lane];
        float q = lrelu(cur + xrc) * ac;
#pragma unroll
        for (int off = 16; off >= 1; off >>= 1) q += __shfl_xor_sync(0xffffffffu, q, off);
        float mn = fmaxf(m, q);
        float sc = __expf(m - mn);
        float w = __expf(q - mn);
        lsum = lsum * sc + w;
        acc = acc * sc + w * cur;
        m = mn;
    }
    g_h2e[node * 32 + lane] = eluf(acc / lsum + b2[lane]);
}

// ---------------- launch ----------------
extern "C" void kernel_launch(void* const* d_in, const int* in_sizes, int n_in,
                              void* d_out, int out_size) {
    const float* x     = (const float*)d_in[0];
    const int*   ei    = (const int*)d_in[1];
    const float* W1l   = (const float*)d_in[2];
    const float* W1r   = (const float*)d_in[3];
    const float* att1  = (const float*)d_in[4];
    const float* b1    = (const float*)d_in[5];
    const float* gamma = (const float*)d_in[6];
    const float* beta  = (const float*)d_in[7];
    const float* W2l   = (const float*)d_in[8];
    const float* W2r   = (const float*)d_in[9];
    const float* att2  = (const float*)d_in[10];
    const float* b2    = (const float*)d_in[11];
    const float* Wc    = (const float*)d_in[12];
    const float* bc    = (const float*)d_in[13];
    float* out = (float*)d_out;

    const int n = in_sizes[0] / IN_CH;   // 50000
    const int e = in_sizes[1] / 2;       // 800000

    // --- prep (zero + weight concat) + CSR build ---
    k_prep<<<(n + 255) / 256, 256>>>(W1l, W1r, W2l, W2r, n);
    k_count<<<(e + 255) / 256, 256>>>(ei, e);
    k_scan_all<<<1, 1024>>>(n, e);
    k_fill<<<(e + 255) / 256, 256>>>(ei, e);

    // --- conv1 projection (fused l|r): xlr1 = x @ [W1l|W1r] ---
    dim3 g1((n + 127) / 128, 2);
    k_gemm1<<<g1, 256>>>(x, n);

    // --- conv1 edge softmax + aggregate (+b1) ---
    k_gat1_agg<<<(n + 7) / 8, 256>>>(att1, b1, n);

    // --- BN stats (applied inline in gemm2's A load) ---
    k_bn_stats<<<256, 128>>>(n);
    k_bn_final<<<1, 128>>>(gamma, beta, n);

    // --- conv2 projection: xlr2 = elu(bn(h1)) @ [W2l|W2r] ---
    dim3 g2((n + 127) / 128, 1);
    k_gemm2<<<g2, 256>>>(n);

    // --- conv2 edge softmax + aggregate, +b2, ELU ---
    k_gat2_agg<<<(n + 7) / 8, 256>>>(att2, b2, n);

    // --- classifier: out = [h2e | x] @ Wc + bc ---
    k_gemm3<<<g2, 256>>>(Wc, bc, x, out, n);
}

// round 7
// speedup vs baseline: 1.2315x; 1.2315x over previous
#include <cuda_runtime.h>
#include <math.h>
#include <stdint.h>

// ---------------- problem constants ----------------
#define N_MAX   50000
#define E_MAX   800000
#define IN_CH   128
#define HIDC    32
#define H1CH    128      // heads1 * hid
#define CATCH   160
#define OUTCH   64
#define NEG_SLOPE 0.2f
#define BN_EPS    1e-5f

// ---------------- device scratch (no allocs allowed) ----------------
__device__ float g_xlr1[N_MAX * 256];   // [xl1 | xr1] per row
__device__ float g_h1  [N_MAX * H1CH];
__device__ float g_xlr2[N_MAX * 64];
__device__ float g_h2e [N_MAX * HIDC];
__device__ float g_w1cat[128 * 256];
__device__ float g_w2cat[128 * 64];

__device__ int   g_counts[N_MAX];
__device__ int   g_incl  [N_MAX];
__device__ int   g_rowptr[N_MAX + 1];
__device__ int   g_srcs  [E_MAX];
__device__ int   g_bsums [64];
__device__ int   g_boff  [64];

__device__ float g_sum  [H1CH];
__device__ float g_sumsq[H1CH];
__device__ float g_scale[H1CH];
__device__ float g_shift[H1CH];

// ---------------- helpers ----------------
__device__ __forceinline__ float lrelu(float v) { return v > 0.f ? v : NEG_SLOPE * v; }
__device__ __forceinline__ float eluf(float v)  { return v > 0.f ? v : expm1f(v); }

__device__ __forceinline__ uint32_t f2tf32(float f) {
    uint32_t u;
    asm("cvt.rna.tf32.f32 %0, %1;" : "=r"(u) : "f"(f));
    return u;
}

__device__ __forceinline__ uint4 f4_to_tf32(float4 v) {
    uint4 r;
    r.x = f2tf32(v.x); r.y = f2tf32(v.y); r.z = f2tf32(v.z); r.w = f2tf32(v.w);
    return r;
}

__device__ __forceinline__ void mma_m16n8k8(float* c, const uint32_t* a, const uint32_t* b) {
    asm volatile(
        "mma.sync.aligned.m16n8k8.row.col.f32.tf32.tf32.f32 "
        "{%0,%1,%2,%3}, {%4,%5,%6,%7}, {%8,%9}, {%0,%1,%2,%3};\n"
        : "+f"(c[0]), "+f"(c[1]), "+f"(c[2]), "+f"(c[3])
        : "r"(a[0]), "r"(a[1]), "r"(a[2]), "r"(a[3]), "r"(b[0]), "r"(b[1]));
}

// ---------------- prep: zero counters + concat weights (coalesced) ----------------
__global__ void k_prep(const float* __restrict__ W1l, const float* __restrict__ W1r,
                       const float* __restrict__ W2l, const float* __restrict__ W2r, int n) {
    int i = blockIdx.x * blockDim.x + threadIdx.x;
    if (i < n) g_counts[i] = 0;
    if (i < H1CH) { g_sum[i] = 0.f; g_sumsq[i] = 0.f; }
    if (i < 128 * 256) {
        int k = i >> 8, j = i & 255;
        g_w1cat[i] = (j < 128) ? W1l[k * 128 + j] : W1r[k * 128 + j - 128];
    }
    if (i < 128 * 64) {
        int k = i >> 6, j = i & 63;
        g_w2cat[i] = (j < 32) ? W2l[k * 32 + j] : W2r[k * 32 + (j - 32)];
    }
}

// ---------------- CSR build (multi-block, coalesced scan) ----------------
__global__ void k_count(const int* __restrict__ ei, int e) {
    int i = blockIdx.x * blockDim.x + threadIdx.x;
    if (i < e) atomicAdd(&g_counts[ei[e + i]], 1);
}

__global__ void k_scan1(int n) {
    __shared__ int sh[1024];
    int i = blockIdx.x * 1024 + threadIdx.x;
    int v = (i < n) ? g_counts[i] : 0;
    sh[threadIdx.x] = v;
    __syncthreads();
    for (int off = 1; off < 1024; off <<= 1) {
        int t = (threadIdx.x >= off) ? sh[threadIdx.x - off] : 0;
        __syncthreads();
        sh[threadIdx.x] += t;
        __syncthreads();
    }
    if (i < n) g_incl[i] = sh[threadIdx.x];
    if (threadIdx.x == 1023) g_bsums[blockIdx.x] = sh[1023];
}

__global__ void k_scan2(int nb) {
    int t = threadIdx.x;               // 64 threads, 2 warps
    int v = (t < nb) ? g_bsums[t] : 0;
    int lane = t & 31, w = t >> 5;
    int s = v;
#pragma unroll
    for (int off = 1; off < 32; off <<= 1) {
        int u = __shfl_up_sync(0xffffffffu, s, off);
        if (lane >= off) s += u;
    }
    __shared__ int wtot;
    if (w == 0 && lane == 31) wtot = s;
    __syncthreads();
    int base = (w == 1) ? wtot : 0;
    if (t < nb) g_boff[t] = base + s - v;   // exclusive prefix of block sums
}

__global__ void k_scan3(int n, int e) {
    int i = blockIdx.x * 1024 + threadIdx.x;
    if (i < n) {
        int c = g_counts[i];
        int boff = g_boff[blockIdx.x];
        g_rowptr[i] = g_incl[i] - c + boff;
        g_counts[i] = 0;
        if (i == n - 1) g_rowptr[n] = e;
    }
}

__global__ void k_fill(const int* __restrict__ ei, int e) {
    int i = blockIdx.x * blockDim.x + threadIdx.x;
    if (i < e) {
        int d = ei[e + i];
        int s = ei[i];
        int pos = g_rowptr[d] + atomicAdd(&g_counts[d], 1);
        g_srcs[pos] = s;
    }
}

// ---------------- tf32 MMA GEMM (smem holds tf32 bits) ----------------
// MODE 0: A = plain fp32 pointer
// MODE 1: A = elu(bn(g_h1))   (K=128)
// MODE 2: A = [g_h2e | xcat]  (K=160)
template <int BM, int BN, int WM_CNT, int WN_CNT, int MODE>
__device__ __forceinline__ void mma_gemm_body(
    const float* __restrict__ A, const float* __restrict__ B,
    float* __restrict__ C, int M, int K, int ldb, int ldc,
    const float* __restrict__ bias, const float* __restrict__ xcat)
{
    constexpr int BK = 32;
    constexpr int THREADS = WM_CNT * WN_CNT * 32;
    constexpr int WM = BM / WM_CNT;
    constexpr int WN = BN / WN_CNT;
    constexpr int MT = WM / 16;
    constexpr int NT = WN / 8;
    constexpr int LDA = BK + 4;
    constexpr int LDB = BN + 8;

    __shared__ uint32_t As[BM][LDA];
    __shared__ uint32_t Bs[BK][LDB];

    const int tid = threadIdx.x;
    const int wid = tid >> 5;
    const int lane = tid & 31;
    const int warpM = wid / WN_CNT;
    const int warpN = wid % WN_CNT;
    const int g = lane >> 2;
    const int tg = lane & 3;

    const int rowBase = blockIdx.x * BM;
    const int colBase = blockIdx.y * BN;

    float acc[MT][NT][4];
#pragma unroll
    for (int mt = 0; mt < MT; mt++)
#pragma unroll
        for (int nt = 0; nt < NT; nt++)
#pragma unroll
            for (int i = 0; i < 4; i++) acc[mt][nt][i] = 0.f;

    for (int kt = 0; kt < K; kt += BK) {
        constexpr int A_F4 = BM * BK / 4;
#pragma unroll
        for (int it = 0; it < A_F4 / THREADS; it++) {
            int f = tid + it * THREADS;
            int r = f >> 3;
            int kq = (f & 7) << 2;
            int grow = rowBase + r;
            float4 v = make_float4(0.f, 0.f, 0.f, 0.f);
            if (grow < M) {
                if (MODE == 0) {
                    v = *reinterpret_cast<const float4*>(A + (size_t)grow * K + kt + kq);
                } else if (MODE == 1) {
                    v = *reinterpret_cast<const float4*>(&g_h1[(size_t)grow * 128 + kt + kq]);
                    int c = kt + kq;
                    v.x = eluf(fmaf(v.x, g_scale[c + 0], g_shift[c + 0]));
                    v.y = eluf(fmaf(v.y, g_scale[c + 1], g_shift[c + 1]));
                    v.z = eluf(fmaf(v.z, g_scale[c + 2], g_shift[c + 2]));
                    v.w = eluf(fmaf(v.w, g_scale[c + 3], g_shift[c + 3]));
                } else {
                    if (kt == 0)
                        v = *reinterpret_cast<const float4*>(&g_h2e[(size_t)grow * 32 + kq]);
                    else
                        v = *reinterpret_cast<const float4*>(&xcat[(size_t)grow * 128 + kt - 32 + kq]);
                }
            }
            *reinterpret_cast<uint4*>(&As[r][kq]) = f4_to_tf32(v);
        }
        constexpr int B_F4 = BK * BN / 4;
#pragma unroll
        for (int it = 0; it < B_F4 / THREADS; it++) {
            int f = tid + it * THREADS;
            int kr = f / (BN / 4);
            int nq = (f % (BN / 4)) << 2;
            float4 v = *reinterpret_cast<const float4*>(B + (size_t)(kt + kr) * ldb + colBase + nq);
            *reinterpret_cast<uint4*>(&Bs[kr][nq]) = f4_to_tf32(v);
        }
        __syncthreads();

#pragma unroll
        for (int kk = 0; kk < BK; kk += 8) {
            uint32_t af[MT][4];
#pragma unroll
            for (int mt = 0; mt < MT; mt++) {
                int m = warpM * WM + mt * 16;
                af[mt][0] = As[m + g][kk + tg];
                af[mt][1] = As[m + g + 8][kk + tg];
                af[mt][2] = As[m + g][kk + tg + 4];
                af[mt][3] = As[m + g + 8][kk + tg + 4];
            }
            uint32_t bf[NT][2];
#pragma unroll
            for (int nt = 0; nt < NT; nt++) {
                int nn = warpN * WN + nt * 8;
                bf[nt][0] = Bs[kk + tg][nn + g];
                bf[nt][1] = Bs[kk + tg + 4][nn + g];
            }
#pragma unroll
            for (int mt = 0; mt < MT; mt++)
#pragma unroll
                for (int nt = 0; nt < NT; nt++)
                    mma_m16n8k8(acc[mt][nt], af[mt], bf[nt]);
        }
        __syncthreads();
    }

#pragma unroll
    for (int mt = 0; mt < MT; mt++) {
        int m0 = rowBase + warpM * WM + mt * 16 + g;
        int m1 = m0 + 8;
#pragma unroll
        for (int nt = 0; nt < NT; nt++) {
            int c0 = colBase + warpN * WN + nt * 8 + 2 * tg;
            float bx = 0.f, by = 0.f;
            if (bias) { bx = bias[c0]; by = bias[c0 + 1]; }
            if (m0 < M) {
                float2 v = make_float2(acc[mt][nt][0] + bx, acc[mt][nt][1] + by);
                *reinterpret_cast<float2*>(&C[(size_t)m0 * ldc + c0]) = v;
            }
            if (m1 < M) {
                float2 v = make_float2(acc[mt][nt][2] + bx, acc[mt][nt][3] + by);
                *reinterpret_cast<float2*>(&C[(size_t)m1 * ldc + c0]) = v;
            }
        }
    }
}

__global__ void __launch_bounds__(256) k_gemm1(const float* __restrict__ x, int M) {
    mma_gemm_body<128, 128, 2, 4, 0>(x, g_w1cat, g_xlr1, M, 128, 256, 256, nullptr, nullptr);
}
__global__ void __launch_bounds__(256) k_gemm2(int M) {
    mma_gemm_body<128, 64, 4, 2, 1>(nullptr, g_w2cat, g_xlr2, M, 128, 64, 64, nullptr, nullptr);
}
__global__ void __launch_bounds__(256) k_gemm3(const float* __restrict__ Wc,
                                               const float* __restrict__ bc,
                                               const float* __restrict__ x,
                                               float* __restrict__ out, int M) {
    mma_gemm_body<128, 64, 4, 2, 2>(nullptr, Wc, out, M, 160, 64, 64, bc, x);
}

// ---------------- GAT layer 1: warp-per-node, online softmax, prefetch ----------------
__global__ void k_gat1_agg(const float* __restrict__ att1, const float* __restrict__ b1, int n) {
    int node = blockIdx.x * (blockDim.x >> 5) + (threadIdx.x >> 5);
    if (node >= n) return;
    int lane = threadIdx.x & 31;

    const float4* xlr = reinterpret_cast<const float4*>(g_xlr1);

    float4 xrv = xlr[node * 64 + 32 + lane];
    float4 attv = *reinterpret_cast<const float4*>(att1 + (lane >> 3) * HIDC + (lane & 7) * 4);

    // self loop first
    float4 msg = xlr[node * 64 + lane];
    float p = lrelu(msg.x + xrv.x) * attv.x + lrelu(msg.y + xrv.y) * attv.y +
              lrelu(msg.z + xrv.z) * attv.z + lrelu(msg.w + xrv.w) * attv.w;
    p += __shfl_xor_sync(0xffffffffu, p, 1);
    p += __shfl_xor_sync(0xffffffffu, p, 2);
    p += __shfl_xor_sync(0xffffffffu, p, 4);

    float m = p;
    float lsum = 1.f;
    float4 acc = msg;

    int beg = g_rowptr[node];
    int end = g_rowptr[node + 1];

    float4 nmsg = make_float4(0.f, 0.f, 0.f, 0.f);
    if (beg < end) nmsg = xlr[g_srcs[beg] * 64 + lane];

    for (int i = beg; i < end; i++) {
        float4 cur = nmsg;
        if (i + 1 < end) nmsg = xlr[g_srcs[i + 1] * 64 + lane];   // prefetch next edge
        float q = lrelu(cur.x + xrv.x) * attv.x + lrelu(cur.y + xrv.y) * attv.y +
                  lrelu(cur.z + xrv.z) * attv.z + lrelu(cur.w + xrv.w) * attv.w;
        q += __shfl_xor_sync(0xffffffffu, q, 1);
        q += __shfl_xor_sync(0xffffffffu, q, 2);
        q += __shfl_xor_sync(0xffffffffu, q, 4);
        float mn = fmaxf(m, q);
        float sc = __expf(m - mn);
        float w = __expf(q - mn);
        lsum = lsum * sc + w;
        acc.x = acc.x * sc + w * cur.x;
        acc.y = acc.y * sc + w * cur.y;
        acc.z = acc.z * sc + w * cur.z;
        acc.w = acc.w * sc + w * cur.w;
        m = mn;
    }

    float inv = 1.f / lsum;
    float4 bvv = *reinterpret_cast<const float4*>(b1 + lane * 4);
    float4 o;
    o.x = acc.x * inv + bvv.x;
    o.y = acc.y * inv + bvv.y;
    o.z = acc.z * inv + bvv.z;
    o.w = acc.w * inv + bvv.w;
    reinterpret_cast<float4*>(g_h1)[node * 32 + lane] = o;
}

// ---------------- BatchNorm stats ----------------
__global__ void k_bn_stats(int n) {
    int c = threadIdx.x;  // 128 threads
    float s = 0.f, q = 0.f;
    for (int r = blockIdx.x; r < n; r += gridDim.x) {
        float v = g_h1[(size_t)r * H1CH + c];
        s += v;
        q += v * v;
    }
    atomicAdd(&g_sum[c], s);
    atomicAdd(&g_sumsq[c], q);
}

__global__ void k_bn_final(const float* __restrict__ gamma, const float* __restrict__ beta, int n) {
    int c = threadIdx.x;
    if (c < H1CH) {
        float mu = g_sum[c] / (float)n;
        float var = g_sumsq[c] / (float)n - mu * mu;
        float rs = rsqrtf(var + BN_EPS);
        float sc = rs * gamma[c];
        g_scale[c] = sc;
        g_shift[c] = beta[c] - mu * sc;
    }
}

// ---------------- GAT layer 2 (1 head, 32 ch), prefetch ----------------
__global__ void k_gat2_agg(const float* __restrict__ att2, const float* __restrict__ b2, int n) {
    int node = blockIdx.x * (blockDim.x >> 5) + (threadIdx.x >> 5);
    if (node >= n) return;
    int lane = threadIdx.x & 31;

    float xrc = g_xlr2[node * 64 + 32 + lane];
    float ac = att2[lane];

    float msg = g_xlr2[node * 64 + lane];
    float p = lrelu(msg + xrc) * ac;
#pragma unroll
    for (int off = 16; off >= 1; off >>= 1) p += __shfl_xor_sync(0xffffffffu, p, off);

    float m = p, lsum = 1.f, acc = msg;

    int beg = g_rowptr[node];
    int end = g_rowptr[node + 1];

    float nmsg = 0.f;
    if (beg < end) nmsg = g_xlr2[g_srcs[beg] * 64 + lane];

    for (int i = beg; i < end; i++) {
        float cur = nmsg;
        if (i + 1 < end) nmsg = g_xlr2[g_srcs[i + 1] * 64 + lane];
        float q = lrelu(cur + xrc) * ac;
#pragma unroll
        for (int off = 16; off >= 1; off >>= 1) q += __shfl_xor_sync(0xffffffffu, q, off);
        float mn = fmaxf(m, q);
        float sc = __expf(m - mn);
        float w = __expf(q - mn);
        lsum = lsum * sc + w;
        acc = acc * sc + w * cur;
        m = mn;
    }
    g_h2e[node * 32 + lane] = eluf(acc / lsum + b2[lane]);
}

// ---------------- launch ----------------
extern "C" void kernel_launch(void* const* d_in, const int* in_sizes, int n_in,
                              void* d_out, int out_size) {
    const float* x     = (const float*)d_in[0];
    const int*   ei    = (const int*)d_in[1];
    const float* W1l   = (const float*)d_in[2];
    const float* W1r   = (const float*)d_in[3];
    const float* att1  = (const float*)d_in[4];
    const float* b1    = (const float*)d_in[5];
    const float* gamma = (const float*)d_in[6];
    const float* beta  = (const float*)d_in[7];
    const float* W2l   = (const float*)d_in[8];
    const float* W2r   = (const float*)d_in[9];
    const float* att2  = (const float*)d_in[10];
    const float* b2    = (const float*)d_in[11];
    const float* Wc    = (const float*)d_in[12];
    const float* bc    = (const float*)d_in[13];
    float* out = (float*)d_out;

    const int n = in_sizes[0] / IN_CH;   // 50000
    const int e = in_sizes[1] / 2;       // 800000
    const int nb = (n + 1023) / 1024;

    // --- prep (zero + weight concat) + CSR build (coalesced multi-block scan) ---
    k_prep<<<(n + 255) / 256, 256>>>(W1l, W1r, W2l, W2r, n);
    k_count<<<(e + 255) / 256, 256>>>(ei, e);
    k_scan1<<<nb, 1024>>>(n);
    k_scan2<<<1, 64>>>(nb);
    k_scan3<<<nb, 1024>>>(n, e);
    k_fill<<<(e + 255) / 256, 256>>>(ei, e);

    // --- conv1 projection (fused l|r): xlr1 = x @ [W1l|W1r] ---
    dim3 g1((n + 127) / 128, 2);
    k_gemm1<<<g1, 256>>>(x, n);

    // --- conv1 edge softmax + aggregate (+b1) ---
    k_gat1_agg<<<(n + 7) / 8, 256>>>(att1, b1, n);

    // --- BN stats (applied inline in gemm2's A load) ---
    k_bn_stats<<<256, 128>>>(n);
    k_bn_final<<<1, 128>>>(gamma, beta, n);

    // --- conv2 projection: xlr2 = elu(bn(h1)) @ [W2l|W2r] ---
    dim3 g2((n + 127) / 128, 1);
    k_gemm2<<<g2, 256>>>(n);

    // --- conv2 edge softmax + aggregate, +b2, ELU ---
    k_gat2_agg<<<(n + 7) / 8, 256>>>(att2, b2, n);

    // --- classifier: out = [h2e | x] @ Wc + bc ---
    k_gemm3<<<g2, 256>>>(Wc, bc, x, out, n);
}

// round 8
// speedup vs baseline: 1.4433x; 1.1720x over previous
#include <cuda_runtime.h>
#include <cuda_fp16.h>
#include <math.h>
#include <stdint.h>

// ---------------- problem constants ----------------
#define N_MAX   50000
#define E_MAX   800000
#define IN_CH   128
#define HIDC    32
#define H1CH    128      // heads1 * hid
#define CATCH   160
#define OUTCH   64
#define NEG_SLOPE 0.2f
#define BN_EPS    1e-5f

// ---------------- device scratch (no allocs allowed) ----------------
__device__ __half g_xl1h[N_MAX * 128];  // conv1 xl projection, fp16 (gathered per-edge)
__device__ float  g_xr1 [N_MAX * 128];  // conv1 xr projection, fp32 (read once per node)
__device__ float  g_h1  [N_MAX * H1CH];
__device__ float  g_xlr2[N_MAX * 64];
__device__ float  g_h2e [N_MAX * HIDC];
__device__ float  g_w1cat[128 * 256];
__device__ float  g_w2cat[128 * 64];

__device__ int   g_counts[N_MAX];
__device__ int   g_incl  [N_MAX];
__device__ int   g_rowptr[N_MAX + 1];
__device__ int   g_srcs  [E_MAX];
__device__ int   g_bsums [64];
__device__ int   g_boff  [64];

__device__ float g_sum  [H1CH];
__device__ float g_sumsq[H1CH];
__device__ float g_scale[H1CH];
__device__ float g_shift[H1CH];

// ---------------- helpers ----------------
__device__ __forceinline__ float lrelu(float v) { return v > 0.f ? v : NEG_SLOPE * v; }
__device__ __forceinline__ float eluf(float v)  { return v > 0.f ? v : expm1f(v); }

__device__ __forceinline__ uint32_t f2tf32(float f) {
    uint32_t u;
    asm("cvt.rna.tf32.f32 %0, %1;" : "=r"(u) : "f"(f));
    return u;
}

__device__ __forceinline__ uint4 f4_to_tf32(float4 v) {
    uint4 r;
    r.x = f2tf32(v.x); r.y = f2tf32(v.y); r.z = f2tf32(v.z); r.w = f2tf32(v.w);
    return r;
}

__device__ __forceinline__ void mma_m16n8k8(float* c, const uint32_t* a, const uint32_t* b) {
    asm volatile(
        "mma.sync.aligned.m16n8k8.row.col.f32.tf32.tf32.f32 "
        "{%0,%1,%2,%3}, {%4,%5,%6,%7}, {%8,%9}, {%0,%1,%2,%3};\n"
        : "+f"(c[0]), "+f"(c[1]), "+f"(c[2]), "+f"(c[3])
        : "r"(a[0]), "r"(a[1]), "r"(a[2]), "r"(a[3]), "r"(b[0]), "r"(b[1]));
}

// ---------------- prep: zero counters + concat weights (coalesced) ----------------
__global__ void k_prep(const float* __restrict__ W1l, const float* __restrict__ W1r,
                       const float* __restrict__ W2l, const float* __restrict__ W2r, int n) {
    int i = blockIdx.x * blockDim.x + threadIdx.x;
    if (i < n) g_counts[i] = 0;
    if (i < H1CH) { g_sum[i] = 0.f; g_sumsq[i] = 0.f; }
    if (i < 128 * 256) {
        int k = i >> 8, j = i & 255;
        g_w1cat[i] = (j < 128) ? W1l[k * 128 + j] : W1r[k * 128 + j - 128];
    }
    if (i < 128 * 64) {
        int k = i >> 6, j = i & 63;
        g_w2cat[i] = (j < 32) ? W2l[k * 32 + j] : W2r[k * 32 + (j - 32)];
    }
}

// ---------------- CSR build (multi-block, coalesced scan) ----------------
__global__ void k_count(const int* __restrict__ ei, int e) {
    int i = blockIdx.x * blockDim.x + threadIdx.x;
    if (i < e) atomicAdd(&g_counts[ei[e + i]], 1);
}

__global__ void k_scan1(int n) {
    __shared__ int sh[1024];
    int i = blockIdx.x * 1024 + threadIdx.x;
    int v = (i < n) ? g_counts[i] : 0;
    sh[threadIdx.x] = v;
    __syncthreads();
    for (int off = 1; off < 1024; off <<= 1) {
        int t = (threadIdx.x >= off) ? sh[threadIdx.x - off] : 0;
        __syncthreads();
        sh[threadIdx.x] += t;
        __syncthreads();
    }
    if (i < n) g_incl[i] = sh[threadIdx.x];
    if (threadIdx.x == 1023) g_bsums[blockIdx.x] = sh[1023];
}

__global__ void k_scan2(int nb) {
    int t = threadIdx.x;               // 64 threads, 2 warps
    int v = (t < nb) ? g_bsums[t] : 0;
    int lane = t & 31, w = t >> 5;
    int s = v;
#pragma unroll
    for (int off = 1; off < 32; off <<= 1) {
        int u = __shfl_up_sync(0xffffffffu, s, off);
        if (lane >= off) s += u;
    }
    __shared__ int wtot;
    if (w == 0 && lane == 31) wtot = s;
    __syncthreads();
    int base = (w == 1) ? wtot : 0;
    if (t < nb) g_boff[t] = base + s - v;   // exclusive prefix of block sums
}

__global__ void k_scan3(int n, int e) {
    int i = blockIdx.x * 1024 + threadIdx.x;
    if (i < n) {
        int c = g_counts[i];
        int boff = g_boff[blockIdx.x];
        g_rowptr[i] = g_incl[i] - c + boff;
        g_counts[i] = 0;
        if (i == n - 1) g_rowptr[n] = e;
    }
}

__global__ void k_fill(const int* __restrict__ ei, int e) {
    int i = blockIdx.x * blockDim.x + threadIdx.x;
    if (i < e) {
        int d = ei[e + i];
        int s = ei[i];
        int pos = g_rowptr[d] + atomicAdd(&g_counts[d], 1);
        g_srcs[pos] = s;
    }
}

// ---------------- tf32 MMA GEMM (smem holds tf32 bits) ----------------
// MODE (input):  0 = plain fp32 A ptr | 1 = elu(bn(g_h1)), K=128 | 2 = [g_h2e | xcat], K=160
// OUTM (output): 0 = fp32 C          | 1 = split: cols<128 -> g_xl1h fp16, cols>=128 -> g_xr1 fp32
template <int BM, int BN, int WM_CNT, int WN_CNT, int MODE, int OUTM>
__device__ __forceinline__ void mma_gemm_body(
    const float* __restrict__ A, const float* __restrict__ B,
    float* __restrict__ C, int M, int K, int ldb, int ldc,
    const float* __restrict__ bias, const float* __restrict__ xcat)
{
    constexpr int BK = 32;
    constexpr int THREADS = WM_CNT * WN_CNT * 32;
    constexpr int WM = BM / WM_CNT;
    constexpr int WN = BN / WN_CNT;
    constexpr int MT = WM / 16;
    constexpr int NT = WN / 8;
    constexpr int LDA = BK + 4;
    constexpr int LDB = BN + 8;

    __shared__ uint32_t As[BM][LDA];
    __shared__ uint32_t Bs[BK][LDB];

    const int tid = threadIdx.x;
    const int wid = tid >> 5;
    const int lane = tid & 31;
    const int warpM = wid / WN_CNT;
    const int warpN = wid % WN_CNT;
    const int g = lane >> 2;
    const int tg = lane & 3;

    const int rowBase = blockIdx.x * BM;
    const int colBase = blockIdx.y * BN;

    float acc[MT][NT][4];
#pragma unroll
    for (int mt = 0; mt < MT; mt++)
#pragma unroll
        for (int nt = 0; nt < NT; nt++)
#pragma unroll
            for (int i = 0; i < 4; i++) acc[mt][nt][i] = 0.f;

    for (int kt = 0; kt < K; kt += BK) {
        constexpr int A_F4 = BM * BK / 4;
#pragma unroll
        for (int it = 0; it < A_F4 / THREADS; it++) {
            int f = tid + it * THREADS;
            int r = f >> 3;
            int kq = (f & 7) << 2;
            int grow = rowBase + r;
            float4 v = make_float4(0.f, 0.f, 0.f, 0.f);
            if (grow < M) {
                if (MODE == 0) {
                    v = *reinterpret_cast<const float4*>(A + (size_t)grow * K + kt + kq);
                } else if (MODE == 1) {
                    v = *reinterpret_cast<const float4*>(&g_h1[(size_t)grow * 128 + kt + kq]);
                    int c = kt + kq;
                    v.x = eluf(fmaf(v.x, g_scale[c + 0], g_shift[c + 0]));
                    v.y = eluf(fmaf(v.y, g_scale[c + 1], g_shift[c + 1]));
                    v.z = eluf(fmaf(v.z, g_scale[c + 2], g_shift[c + 2]));
                    v.w = eluf(fmaf(v.w, g_scale[c + 3], g_shift[c + 3]));
                } else {
                    if (kt == 0)
                        v = *reinterpret_cast<const float4*>(&g_h2e[(size_t)grow * 32 + kq]);
                    else
                        v = *reinterpret_cast<const float4*>(&xcat[(size_t)grow * 128 + kt - 32 + kq]);
                }
            }
            *reinterpret_cast<uint4*>(&As[r][kq]) = f4_to_tf32(v);
        }
        constexpr int B_F4 = BK * BN / 4;
#pragma unroll
        for (int it = 0; it < B_F4 / THREADS; it++) {
            int f = tid + it * THREADS;
            int kr = f / (BN / 4);
            int nq = (f % (BN / 4)) << 2;
            float4 v = *reinterpret_cast<const float4*>(B + (size_t)(kt + kr) * ldb + colBase + nq);
            *reinterpret_cast<uint4*>(&Bs[kr][nq]) = f4_to_tf32(v);
        }
        __syncthreads();

#pragma unroll
        for (int kk = 0; kk < BK; kk += 8) {
            uint32_t af[MT][4];
#pragma unroll
            for (int mt = 0; mt < MT; mt++) {
                int m = warpM * WM + mt * 16;
                af[mt][0] = As[m + g][kk + tg];
                af[mt][1] = As[m + g + 8][kk + tg];
                af[mt][2] = As[m + g][kk + tg + 4];
                af[mt][3] = As[m + g + 8][kk + tg + 4];
            }
            uint32_t bf[NT][2];
#pragma unroll
            for (int nt = 0; nt < NT; nt++) {
                int nn = warpN * WN + nt * 8;
                bf[nt][0] = Bs[kk + tg][nn + g];
                bf[nt][1] = Bs[kk + tg + 4][nn + g];
            }
#pragma unroll
            for (int mt = 0; mt < MT; mt++)
#pragma unroll
                for (int nt = 0; nt < NT; nt++)
                    mma_m16n8k8(acc[mt][nt], af[mt], bf[nt]);
        }
        __syncthreads();
    }

#pragma unroll
    for (int mt = 0; mt < MT; mt++) {
        int m0 = rowBase + warpM * WM + mt * 16 + g;
        int m1 = m0 + 8;
#pragma unroll
        for (int nt = 0; nt < NT; nt++) {
            int c0 = colBase + warpN * WN + nt * 8 + 2 * tg;
            float bx = 0.f, by = 0.f;
            if (bias) { bx = bias[c0]; by = bias[c0 + 1]; }
            float2 v0 = make_float2(acc[mt][nt][0] + bx, acc[mt][nt][1] + by);
            float2 v1 = make_float2(acc[mt][nt][2] + bx, acc[mt][nt][3] + by);
            if (OUTM == 0) {
                if (m0 < M) *reinterpret_cast<float2*>(&C[(size_t)m0 * ldc + c0]) = v0;
                if (m1 < M) *reinterpret_cast<float2*>(&C[(size_t)m1 * ldc + c0]) = v1;
            } else {
                if (colBase < 128) {   // xl -> fp16
                    if (m0 < M) *reinterpret_cast<__half2*>(&g_xl1h[(size_t)m0 * 128 + c0]) = __floats2half2_rn(v0.x, v0.y);
                    if (m1 < M) *reinterpret_cast<__half2*>(&g_xl1h[(size_t)m1 * 128 + c0]) = __floats2half2_rn(v1.x, v1.y);
                } else {               // xr -> fp32
                    int cc = c0 - 128;
                    if (m0 < M) *reinterpret_cast<float2*>(&g_xr1[(size_t)m0 * 128 + cc]) = v0;
                    if (m1 < M) *reinterpret_cast<float2*>(&g_xr1[(size_t)m1 * 128 + cc]) = v1;
                }
            }
        }
    }
}

__global__ void __launch_bounds__(256) k_gemm1(const float* __restrict__ x, int M) {
    mma_gemm_body<128, 128, 2, 4, 0, 1>(x, g_w1cat, nullptr, M, 128, 256, 0, nullptr, nullptr);
}
__global__ void __launch_bounds__(256) k_gemm2(int M) {
    mma_gemm_body<128, 64, 4, 2, 1, 0>(nullptr, g_w2cat, g_xlr2, M, 128, 64, 64, nullptr, nullptr);
}
__global__ void __launch_bounds__(256) k_gemm3(const float* __restrict__ Wc,
                                               const float* __restrict__ bc,
                                               const float* __restrict__ x,
                                               float* __restrict__ out, int M) {
    mma_gemm_body<128, 64, 4, 2, 2, 0>(nullptr, Wc, out, M, 160, 64, 64, bc, x);
}

// ---------------- GAT layer 1: warp-per-node, fp16 gather, fused BN stats ----------------
__device__ __forceinline__ float4 ldxl_h(int row, int lane) {
    uint2 raw = *reinterpret_cast<const uint2*>(&g_xl1h[(size_t)row * 128 + lane * 4]);
    __half2 h0 = *reinterpret_cast<__half2*>(&raw.x);
    __half2 h1 = *reinterpret_cast<__half2*>(&raw.y);
    float2 f0 = __half22float2(h0);
    float2 f1 = __half22float2(h1);
    return make_float4(f0.x, f0.y, f1.x, f1.y);
}

__global__ void k_gat1_agg(const float* __restrict__ att1, const float* __restrict__ b1, int n) {
    __shared__ float ssum[128], ssq[128];
    int tid = threadIdx.x;
    if (tid < 128) { ssum[tid] = 0.f; ssq[tid] = 0.f; }
    __syncthreads();

    int node = blockIdx.x * (blockDim.x >> 5) + (tid >> 5);
    int lane = tid & 31;
    bool active = (node < n);

    if (active) {
        float4 xrv = *reinterpret_cast<const float4*>(&g_xr1[(size_t)node * 128 + lane * 4]);
        float4 attv = *reinterpret_cast<const float4*>(att1 + (lane >> 3) * HIDC + (lane & 7) * 4);

        // self loop first
        float4 msg = ldxl_h(node, lane);
        float p = lrelu(msg.x + xrv.x) * attv.x + lrelu(msg.y + xrv.y) * attv.y +
                  lrelu(msg.z + xrv.z) * attv.z + lrelu(msg.w + xrv.w) * attv.w;
        p += __shfl_xor_sync(0xffffffffu, p, 1);
        p += __shfl_xor_sync(0xffffffffu, p, 2);
        p += __shfl_xor_sync(0xffffffffu, p, 4);

        float m = p;
        float lsum = 1.f;
        float4 acc = msg;

        int beg = g_rowptr[node];
        int end = g_rowptr[node + 1];

        float4 nmsg = make_float4(0.f, 0.f, 0.f, 0.f);
        if (beg < end) nmsg = ldxl_h(g_srcs[beg], lane);

        for (int i = beg; i < end; i++) {
            float4 cur = nmsg;
            if (i + 1 < end) nmsg = ldxl_h(g_srcs[i + 1], lane);   // prefetch next edge
            float q = lrelu(cur.x + xrv.x) * attv.x + lrelu(cur.y + xrv.y) * attv.y +
                      lrelu(cur.z + xrv.z) * attv.z + lrelu(cur.w + xrv.w) * attv.w;
            q += __shfl_xor_sync(0xffffffffu, q, 1);
            q += __shfl_xor_sync(0xffffffffu, q, 2);
            q += __shfl_xor_sync(0xffffffffu, q, 4);
            float mn = fmaxf(m, q);
            float sc = __expf(m - mn);
            float w = __expf(q - mn);
            lsum = lsum * sc + w;
            acc.x = acc.x * sc + w * cur.x;
            acc.y = acc.y * sc + w * cur.y;
            acc.z = acc.z * sc + w * cur.z;
            acc.w = acc.w * sc + w * cur.w;
            m = mn;
        }

        float inv = 1.f / lsum;
        float4 bvv = *reinterpret_cast<const float4*>(b1 + lane * 4);
        float4 o;
        o.x = acc.x * inv + bvv.x;
        o.y = acc.y * inv + bvv.y;
        o.z = acc.z * inv + bvv.z;
        o.w = acc.w * inv + bvv.w;
        reinterpret_cast<float4*>(g_h1)[node * 32 + lane] = o;

        // block-local BN stats
        int c = lane * 4;
        atomicAdd(&ssum[c + 0], o.x); atomicAdd(&ssq[c + 0], o.x * o.x);
        atomicAdd(&ssum[c + 1], o.y); atomicAdd(&ssq[c + 1], o.y * o.y);
        atomicAdd(&ssum[c + 2], o.z); atomicAdd(&ssq[c + 2], o.z * o.z);
        atomicAdd(&ssum[c + 3], o.w); atomicAdd(&ssq[c + 3], o.w * o.w);
    }

    __syncthreads();
    if (tid < 128) {
        atomicAdd(&g_sum[tid], ssum[tid]);
        atomicAdd(&g_sumsq[tid], ssq[tid]);
    }
}

__global__ void k_bn_final(const float* __restrict__ gamma, const float* __restrict__ beta, int n) {
    int c = threadIdx.x;
    if (c < H1CH) {
        float mu = g_sum[c] / (float)n;
        float var = g_sumsq[c] / (float)n - mu * mu;
        float rs = rsqrtf(var + BN_EPS);
        float sc = rs * gamma[c];
        g_scale[c] = sc;
        g_shift[c] = beta[c] - mu * sc;
    }
}

// ---------------- GAT layer 2 (1 head, 32 ch), prefetch ----------------
__global__ void k_gat2_agg(const float* __restrict__ att2, const float* __restrict__ b2, int n) {
    int node = blockIdx.x * (blockDim.x >> 5) + (threadIdx.x >> 5);
    if (node >= n) return;
    int lane = threadIdx.x & 31;

    float xrc = g_xlr2[node * 64 + 32 + lane];
    float ac = att2[lane];

    float msg = g_xlr2[node * 64 + lane];
    float p = lrelu(msg + xrc) * ac;
#pragma unroll
    for (int off = 16; off >= 1; off >>= 1) p += __shfl_xor_sync(0xffffffffu, p, off);

    float m = p, lsum = 1.f, acc = msg;

    int beg = g_rowptr[node];
    int end = g_rowptr[node + 1];

    float nmsg = 0.f;
    if (beg < end) nmsg = g_xlr2[g_srcs[beg] * 64 + lane];

    for (int i = beg; i < end; i++) {
        float cur = nmsg;
        if (i + 1 < end) nmsg = g_xlr2[g_srcs[i + 1] * 64 + lane];
        float q = lrelu(cur + xrc) * ac;
#pragma unroll
        for (int off = 16; off >= 1; off >>= 1) q += __shfl_xor_sync(0xffffffffu, q, off);
        float mn = fmaxf(m, q);
        float sc = __expf(m - mn);
        float w = __expf(q - mn);
        lsum = lsum * sc + w;
        acc = acc * sc + w * cur;
        m = mn;
    }
    g_h2e[node * 32 + lane] = eluf(acc / lsum + b2[lane]);
}

// ---------------- launch ----------------
extern "C" void kernel_launch(void* const* d_in, const int* in_sizes, int n_in,
                              void* d_out, int out_size) {
    const float* x     = (const float*)d_in[0];
    const int*   ei    = (const int*)d_in[1];
    const float* W1l   = (const float*)d_in[2];
    const float* W1r   = (const float*)d_in[3];
    const float* att1  = (const float*)d_in[4];
    const float* b1    = (const float*)d_in[5];
    const float* gamma = (const float*)d_in[6];
    const float* beta  = (const float*)d_in[7];
    const float* W2l   = (const float*)d_in[8];
    const float* W2r   = (const float*)d_in[9];
    const float* att2  = (const float*)d_in[10];
    const float* b2    = (const float*)d_in[11];
    const float* Wc    = (const float*)d_in[12];
    const float* bc    = (const float*)d_in[13];
    float* out = (float*)d_out;

    const int n = in_sizes[0] / IN_CH;   // 50000
    const int e = in_sizes[1] / 2;       // 800000
    const int nb = (n + 1023) / 1024;

    // --- prep (zero + weight concat) + CSR build ---
    k_prep<<<(n + 255) / 256, 256>>>(W1l, W1r, W2l, W2r, n);
    k_count<<<(e + 255) / 256, 256>>>(ei, e);
    k_scan1<<<nb, 1024>>>(n);
    k_scan2<<<1, 64>>>(nb);
    k_scan3<<<nb, 1024>>>(n, e);
    k_fill<<<(e + 255) / 256, 256>>>(ei, e);

    // --- conv1 projection: xl (fp16) + xr (fp32) = x @ [W1l|W1r] ---
    dim3 g1((n + 127) / 128, 2);
    k_gemm1<<<g1, 256>>>(x, n);

    // --- conv1 edge softmax + aggregate (+b1), fused BN stats ---
    k_gat1_agg<<<(n + 7) / 8, 256>>>(att1, b1, n);
    k_bn_final<<<1, 128>>>(gamma, beta, n);

    // --- conv2 projection: xlr2 = elu(bn(h1)) @ [W2l|W2r] ---
    dim3 g2((n + 127) / 128, 1);
    k_gemm2<<<g2, 256>>>(n);

    // --- conv2 edge softmax + aggregate, +b2, ELU ---
    k_gat2_agg<<<(n + 7) / 8, 256>>>(att2, b2, n);

    // --- classifier: out = [h2e | x] @ Wc + bc ---
    k_gemm3<<<g2, 256>>>(Wc, bc, x, out, n);
}